// round 13
// baseline (speedup 1.0000x reference)
#include <cuda_runtime.h>
#include <cuda_fp16.h>
#include <math.h>
#include <stdint.h>

#define B_       4
#define CIN      256
#define COUT     256
#define HW       64
#define P_       4096
#define KK       9
#define CK       2304
#define KC       64              // mod conv chunk
#define NITER    (CK / KC)       // 36
#define KCD      32              // dconv chunk
#define NITERD   (CK / KCD)      // 72

// ---------------- scratch ----------------------------------------------------
__device__ __align__(128) unsigned char g_wA[NITERD * 16384];  // fp16 A (dconv)
__device__ __align__(128) unsigned char g_wM[NITER * 4096];    // fp16 A (mod, M=32)
__device__ float4 g_mw[B_ * P_ * KK];
__device__ int4   g_mi[B_ * P_ * KK];

// ---------------- PTX helpers (portable ISA) ---------------------------------
__device__ __forceinline__ uint32_t smem_u32(const void* p) {
    uint32_t a;
    asm("{ .reg .u64 t; cvta.to.shared.u64 t, %1; cvt.u32.u64 %0, t; }" : "=r"(a) : "l"(p));
    return a;
}
__device__ __forceinline__ void ldsm4(uint32_t* r, uint32_t addr) {
    asm volatile("ldmatrix.sync.aligned.m8n8.x4.shared.b16 {%0,%1,%2,%3}, [%4];"
                 : "=r"(r[0]), "=r"(r[1]), "=r"(r[2]), "=r"(r[3]) : "r"(addr));
}
__device__ __forceinline__ void mma_f16(float* d, const uint32_t* a, const uint32_t* b) {
    asm volatile("mma.sync.aligned.m16n8k16.row.col.f32.f16.f16.f32 "
                 "{%0,%1,%2,%3}, {%4,%5,%6,%7}, {%8,%9}, {%0,%1,%2,%3};"
                 : "+f"(d[0]), "+f"(d[1]), "+f"(d[2]), "+f"(d[3])
                 : "r"(a[0]), "r"(a[1]), "r"(a[2]), "r"(a[3]), "r"(b[0]), "r"(b[1]));
}
__device__ __forceinline__ void cpasync16(uint32_t dst, const void* src) {
    asm volatile("cp.async.cg.shared.global [%0], [%1], 16;" :: "r"(dst), "l"(src));
}
#define CP_COMMIT()  asm volatile("cp.async.commit_group;" ::: "memory")
#define CP_WAIT(n)   asm volatile("cp.async.wait_group %0;" :: "n"(n) : "memory")

// ---------------- smem layouts ------------------------------------------------
// dconv_tc (92160 B): A 3x16384 | B 3x8192 | meta half4 + ushort4
#define AS_OFF   0
#define BS_OFF   49152
#define MWH_OFF  73728             // uint2[9][128]  (half4 weights)
#define MI_OFF   82944             // ushort4[9][128]
#define SMEM_BYTES_D 92160
// mod_tc (77824 B): stage s at s*20480 (A 4096 | B 16384), C at 61440
#define MA(s)    ((s) * 20480)
#define MB(s)    ((s) * 20480 + 4096)
#define MCS_OFF  61440
#define MSMEM_BYTES 77824

// ---------------- kernel 0: prep both A images -------------------------------
__global__ __launch_bounds__(256) void prep_w(const float* __restrict__ wdef,
                                              const float* __restrict__ wmod) {
    int blk = blockIdx.x;
    if (blk < 2304) {
        int idx = blk * 256 + threadIdx.x;
        int o = idx / CK, ck = idx - o * CK;
        __half h = __float2half_rn(wdef[idx]);
        int it = ck >> 5, kl = ck & 31;
        int Mblk = o >> 4, Kb = kl >> 4;
        int a_idx = ((o >> 3) & 1) + 2 * ((kl >> 3) & 1);
        uint32_t byte = (uint32_t)it * 16384u
                      + (uint32_t)(((Mblk * 2 + Kb) * 4 + a_idx) * 128)
                      + (uint32_t)((o & 7) * 16 + (kl & 7) * 2);
        *(unsigned short*)(g_wA + byte) = __half_as_ushort(h);
    } else {
        int idx = (blk - 2304) * 256 + threadIdx.x;
        if (idx >= 32 * CK) return;
        int j = idx / CK, ck = idx - j * CK;
        float v = (j < 27) ? wmod[j * CK + ck] : 0.f;
        __half h = __float2half_rn(v);
        int it = ck >> 6, kl = ck & 63;
        int Mblk = j >> 4, Kb = kl >> 4;
        int a_idx = ((j >> 3) & 1) + 2 * ((kl >> 3) & 1);
        uint32_t byte = (uint32_t)it * 4096u
                      + (uint32_t)(((Mblk * 4 + Kb) * 4 + a_idx) * 128)
                      + (uint32_t)((j & 7) * 16 + (kl & 7) * 2);
        *(unsigned short*)(g_wM + byte) = __half_as_ushort(h);
    }
}

// ---------------- kernel 1: mod conv fp16 1-pass HMMA, reg-pipelined ---------
// CTA: M=32 (27 used), N=128 px. 256 thr = 8 warps (2M x 4N), warp tile 16x32.
__global__ __launch_bounds__(256, 1) void mod_tc(const float* __restrict__ x) {
    extern __shared__ __align__(1024) unsigned char sm[];
    const uint32_t sb = smem_u32(sm);
    const int t  = threadIdx.x;
    const int b  = blockIdx.z;
    const int p0 = blockIdx.x * 128;
    const float* xb = x + ((size_t)b << 20);

    const int lane = t & 31, warp = t >> 5;
    const int wm = warp >> 2, wn = warp & 3;

    float acc[4][4];
#pragma unroll
    for (int a = 0; a < 4; a++)
#pragma unroll
        for (int e = 0; e < 4; e++) acc[a][e] = 0.f;

    const int gp = t & 127;
    const int gq = t >> 7;                 // 0..1
    const int hh = (p0 + gp) >> 6, ww = (p0 + gp) & 63;

    float L[16][2];

    auto ldM = [&](int i) {
        const int ck0 = i * KC;
#pragma unroll
        for (int j = 0; j < 16; j++) {
            int pp  = j * 2 + gq;
            int kk  = ck0 + pp * 2;
            int c0  = (kk * 7282) >> 16;  int tap0 = kk - c0 * 9;
            int kk1 = kk + 1;
            int c1  = (kk1 * 7282) >> 16; int tap1 = kk1 - c1 * 9;
            int ky0 = tap0 / 3, kx0 = tap0 - ky0 * 3;
            int ky1 = tap1 / 3, kx1 = tap1 - ky1 * 3;
            int y0 = hh + ky0 - 1, x0 = ww + kx0 - 1;
            int y1 = hh + ky1 - 1, x1 = ww + kx1 - 1;
            float v0 = 0.f, v1 = 0.f;
            if (y0 >= 0 && y0 < HW && x0 >= 0 && x0 < HW)
                v0 = __ldg(xb + ((size_t)c0 << 12) + (y0 << 6) + x0);
            if (y1 >= 0 && y1 < HW && x1 >= 0 && x1 < HW)
                v1 = __ldg(xb + ((size_t)c1 << 12) + (y1 << 6) + x1);
            L[j][0] = v0; L[j][1] = v1;
        }
    };
    auto cvtM = [&](int i) {
        unsigned char* bs = sm + MB(i % 3);
#pragma unroll
        for (int j = 0; j < 16; j++) {
            int pp = j * 2 + gq;
            __half2 hv = __floats2half2_rn(L[j][0], L[j][1]);
            uint32_t byte = (uint32_t)(((gp >> 3) * 8 + (pp >> 2)) * 128
                                       + (gp & 7) * 16 + (pp & 3) * 4);
            *(uint32_t*)(bs + byte) = *(uint32_t*)&hv;
        }
    };
    auto cpA = [&](int i) {
        cpasync16(sb + MA(i % 3) + t * 16, g_wM + (size_t)i * 4096 + t * 16);
        CP_COMMIT();
    };
    auto consume = [&](int i) {
        const uint32_t as = sb + MA(i % 3);
        const uint32_t bs = sb + MB(i % 3);
        const uint32_t arow = (uint32_t)((lane & 7) * 16);
        const uint32_t gsel = (uint32_t)(lane >> 3);
#pragma unroll
        for (int kb = 0; kb < 4; kb++) {
            uint32_t af[4];
            uint32_t tb = (uint32_t)(((wm * 4 + kb) * 4 + gsel) * 128) + arow;
            ldsm4(af, as + tb);
#pragma unroll
            for (int jj = 0; jj < 2; jj++) {
                int nt = wn * 4 + jj * 2;
                uint32_t tb2 = (uint32_t)(((nt + (gsel >> 1)) * 8 + 2 * kb + (gsel & 1)) * 128) + arow;
                uint32_t bf[4];
                ldsm4(bf, bs + tb2);
#pragma unroll
                for (int nn = 0; nn < 2; nn++)
                    mma_f16(acc[jj * 2 + nn], af, bf + nn * 2);
            }
        }
    };

    ldM(0);  cpA(0);
    cvtM(0);
    ldM(1);  cpA(1);
    CP_WAIT(1);
    __syncthreads();

    for (int i = 0; i < NITER; i++) {
        consume(i);
        if (i + 1 < NITER) cvtM(i + 1);
        if (i + 2 < NITER) { ldM(i + 2); cpA(i + 2); CP_WAIT(1); }
        else               { CP_WAIT(0); }
        __syncthreads();
    }

    // ---- epilogue: stage C, compute bilinear metadata -----------------------
    float* C = (float*)(sm + MCS_OFF);     // [32][128]
    {
        int r0 = wm * 16 + (lane >> 2);
#pragma unroll
        for (int jj = 0; jj < 2; jj++)
#pragma unroll
            for (int nn = 0; nn < 2; nn++) {
                int col = wn * 32 + jj * 16 + nn * 8 + (lane & 3) * 2;
                float* dd = acc[jj * 2 + nn];
                C[r0 * 128 + col]           = dd[0];
                C[r0 * 128 + col + 1]       = dd[1];
                C[(r0 + 8) * 128 + col]     = dd[2];
                C[(r0 + 8) * 128 + col + 1] = dd[3];
            }
    }
    __syncthreads();

    for (int e = t; e < 128 * KK; e += 256) {
        int k = e >> 7, p = e & 127;
        float dy = C[(2 * k) * 128 + p];
        float dx = C[(2 * k + 1) * 128 + p];
        float mz = C[(18 + k) * 128 + p];
        float m  = 1.f / (1.f + expf(-mz));

        int ph = (p0 + p) >> 6, pw = (p0 + p) & 63;
        int ky = k / 3, kx = k - ky * 3;
        float py = dy + (float)(ph - 1 + ky);
        float px = dx + (float)(pw - 1 + kx);
        float y0f = floorf(py), x0f = floorf(px);
        float fy = py - y0f, fx = px - x0f;
        int y0 = (int)y0f, x0 = (int)x0f;
        int y1 = y0 + 1,  x1 = x0 + 1;

        bool vy0 = (y0 >= 0) & (y0 < HW);
        bool vy1 = (y1 >= 0) & (y1 < HW);
        bool vx0 = (x0 >= 0) & (x0 < HW);
        bool vx1 = (x1 >= 0) & (x1 < HW);
        int cy0 = min(max(y0, 0), HW - 1), cy1 = min(max(y1, 0), HW - 1);
        int cx0 = min(max(x0, 0), HW - 1), cx1 = min(max(x1, 0), HW - 1);

        float4 wv;
        wv.x = (vy0 && vx0) ? (1.f - fy) * (1.f - fx) * m : 0.f;
        wv.y = (vy0 && vx1) ? (1.f - fy) * fx         * m : 0.f;
        wv.z = (vy1 && vx0) ? fy * (1.f - fx)         * m : 0.f;
        wv.w = (vy1 && vx1) ? fy * fx                 * m : 0.f;
        int4 iv;
        iv.x = (cy0 << 6) + cx0;
        iv.y = (cy0 << 6) + cx1;
        iv.z = (cy1 << 6) + cx0;
        iv.w = (cy1 << 6) + cx1;

        g_mw[((size_t)b * P_ + p0 + p) * KK + k] = wv;
        g_mi[((size_t)b * P_ + p0 + p) * KK + k] = iv;
    }
}

// ---------------- kernel 2: software-pipelined fp16 HMMA GEMM ----------------
__global__ __launch_bounds__(512, 1) void dconv_tc(const float* __restrict__ x,
                                                   const float* __restrict__ bias,
                                                   float* __restrict__ out) {
    extern __shared__ __align__(1024) unsigned char sm[];
    const uint32_t sb = smem_u32(sm);
    const int t  = threadIdx.x;
    const int b  = blockIdx.z;
    const int p0 = blockIdx.x * 128;
    const float* xb = x + ((size_t)b << 20);

    const int lane = t & 31, warp = t >> 5;
    const int wm = warp >> 1, wn = warp & 1;

    uint2*   s_mwh = (uint2*)(sm + MWH_OFF);    // half4 weights
    ushort4* s_mi  = (ushort4*)(sm + MI_OFF);
    {
        const float4* gw = g_mw + ((size_t)b * P_ + p0) * KK;
        const int4*   gi = g_mi + ((size_t)b * P_ + p0) * KK;
        for (int e = t; e < 128 * KK; e += 512) {
            int tap = e >> 7, p = e & 127;
            float4 w = gw[p * 9 + tap];
            __half2 h01 = __floats2half2_rn(w.x, w.y);
            __half2 h23 = __floats2half2_rn(w.z, w.w);
            s_mwh[e] = make_uint2(*(uint32_t*)&h01, *(uint32_t*)&h23);
            int4 v = gi[p * 9 + tap];
            s_mi[e] = make_ushort4((unsigned short)v.x, (unsigned short)v.y,
                                   (unsigned short)v.z, (unsigned short)v.w);
        }
    }
    __syncthreads();

    float d[2][8][4];
#pragma unroll
    for (int a = 0; a < 2; a++)
#pragma unroll
        for (int c = 0; c < 8; c++)
#pragma unroll
            for (int e = 0; e < 4; e++) d[a][c][e] = 0.f;

    const int gp = t & 127;
    const int gq = t >> 7;
    float L[4][8];

    auto ldB = [&](int i) {
        const int ck0 = i * KCD;
#pragma unroll
        for (int j = 0; j < 4; j++) {
            int pp  = j * 4 + gq;
            int kk  = ck0 + pp * 2;
            int c0  = (kk * 7282) >> 16;  int tap0 = kk - c0 * 9;
            int kk1 = kk + 1;
            int c1  = (kk1 * 7282) >> 16; int tap1 = kk1 - c1 * 9;
            ushort4 i0 = s_mi[tap0 * 128 + gp];
            ushort4 i1 = s_mi[tap1 * 128 + gp];
            const float* xc0 = xb + ((size_t)c0 << 12);
            const float* xc1 = xb + ((size_t)c1 << 12);
            L[j][0] = __ldg(xc0 + i0.x); L[j][1] = __ldg(xc0 + i0.y);
            L[j][2] = __ldg(xc0 + i0.z); L[j][3] = __ldg(xc0 + i0.w);
            L[j][4] = __ldg(xc1 + i1.x); L[j][5] = __ldg(xc1 + i1.y);
            L[j][6] = __ldg(xc1 + i1.z); L[j][7] = __ldg(xc1 + i1.w);
        }
    };
    auto cvtB = [&](int i) {
        const int ck0 = i * KCD;
        unsigned char* bs = sm + BS_OFF + (i % 3) * 8192;
#pragma unroll
        for (int j = 0; j < 4; j++) {
            int pp  = j * 4 + gq;
            int kk  = ck0 + pp * 2;
            int c0  = (kk * 7282) >> 16;  int tap0 = kk - c0 * 9;
            int kk1 = kk + 1;
            int c1  = (kk1 * 7282) >> 16; int tap1 = kk1 - c1 * 9;
            uint2 wp0 = s_mwh[tap0 * 128 + gp];
            uint2 wp1 = s_mwh[tap1 * 128 + gp];
            __half2 a01 = *(__half2*)&wp0.x, a23 = *(__half2*)&wp0.y;
            __half2 b01 = *(__half2*)&wp1.x, b23 = *(__half2*)&wp1.y;
            float g0 = __low2float(a01) * L[j][0] + __high2float(a01) * L[j][1]
                     + __low2float(a23) * L[j][2] + __high2float(a23) * L[j][3];
            float g1 = __low2float(b01) * L[j][4] + __high2float(b01) * L[j][5]
                     + __low2float(b23) * L[j][6] + __high2float(b23) * L[j][7];
            __half2 hv = __floats2half2_rn(g0, g1);
            uint32_t byte = (uint32_t)(((gp >> 3) * 4 + (pp >> 2)) * 128
                                       + (gp & 7) * 16 + (pp & 3) * 4);
            *(uint32_t*)(bs + byte) = *(uint32_t*)&hv;
        }
    };
    auto cpA = [&](int i) {
        uint32_t dst = sb + AS_OFF + (i % 3) * 16384 + t * 32;
        const unsigned char* src = g_wA + (size_t)i * 16384 + t * 32;
        cpasync16(dst, src);
        cpasync16(dst + 16, src + 16);
        CP_COMMIT();
    };
    auto consume = [&](int i) {
        const uint32_t as = sb + AS_OFF + (i % 3) * 16384;
        const uint32_t bs = sb + BS_OFF + (i % 3) * 8192;
        const uint32_t arow = (uint32_t)((lane & 7) * 16);
        const uint32_t gsel = (uint32_t)(lane >> 3);
#pragma unroll
        for (int kb = 0; kb < 2; kb++) {
            uint32_t af[8];
#pragma unroll
            for (int mb = 0; mb < 2; mb++) {
                uint32_t tb = (uint32_t)((((wm * 2 + mb) * 2 + kb) * 4 + gsel) * 128) + arow;
                ldsm4(af + mb * 4, as + tb);
            }
#pragma unroll
            for (int jj = 0; jj < 4; jj++) {
                int nt = wn * 8 + jj * 2;
                uint32_t tb = (uint32_t)(((nt + (gsel >> 1)) * 4 + 2 * kb + (gsel & 1)) * 128) + arow;
                uint32_t bf[4];
                ldsm4(bf, bs + tb);
#pragma unroll
                for (int mb = 0; mb < 2; mb++) {
#pragma unroll
                    for (int nn = 0; nn < 2; nn++)
                        mma_f16(d[mb][jj * 2 + nn], af + mb * 4, bf + nn * 2);
                }
            }
        }
    };

    ldB(0);  cpA(0);
    cvtB(0);
    ldB(1);  cpA(1);
    CP_WAIT(1);
    __syncthreads();

    for (int i = 0; i < NITERD; i++) {
        consume(i);
        if (i + 1 < NITERD) cvtB(i + 1);
        if (i + 2 < NITERD) { ldB(i + 2); cpA(i + 2); CP_WAIT(1); }
        else                { CP_WAIT(0); }
        __syncthreads();
    }

    // epilogue
#pragma unroll
    for (int mb = 0; mb < 2; mb++) {
        int m0 = wm * 32 + mb * 16 + (lane >> 2);
        float bv0 = bias[m0], bv1 = bias[m0 + 8];
        float* r0 = out + (((size_t)(b * COUT + m0)) << 12) + p0 + wn * 64 + (lane & 3) * 2;
        float* r1 = r0 + ((size_t)8 << 12);
#pragma unroll
        for (int nj = 0; nj < 8; nj++) {
            float2 v0 = make_float2(d[mb][nj][0] + bv0, d[mb][nj][1] + bv0);
            float2 v1 = make_float2(d[mb][nj][2] + bv1, d[mb][nj][3] + bv1);
            *(float2*)(r0 + nj * 8) = v0;
            *(float2*)(r1 + nj * 8) = v1;
        }
    }
}

// ---------------- launch ------------------------------------------------------
extern "C" void kernel_launch(void* const* d_in, const int* in_sizes, int n_in,
                              void* d_out, int out_size) {
    const float* x     = (const float*)d_in[0];
    const float* w_mod = (const float*)d_in[1];
    const float* w_def = (const float*)d_in[2];
    const float* b_def = (const float*)d_in[3];
    float* out = (float*)d_out;

    cudaFuncSetAttribute(dconv_tc, cudaFuncAttributeMaxDynamicSharedMemorySize, SMEM_BYTES_D);
    cudaFuncSetAttribute(mod_tc,   cudaFuncAttributeMaxDynamicSharedMemorySize, MSMEM_BYTES);

    prep_w<<<2592, 256>>>(w_def, w_mod);
    mod_tc<<<dim3(P_ / 128, 1, B_), 256, MSMEM_BYTES>>>(x);
    dconv_tc<<<dim3(P_ / 128, 1, B_), 512, SMEM_BYTES_D>>>(x, b_def, out);
}

// round 14
// speedup vs baseline: 1.4775x; 1.4775x over previous
#include <cuda_runtime.h>
#include <cuda_fp16.h>
#include <math.h>
#include <stdint.h>

#define B_       4
#define CIN      256
#define COUT     256
#define HW       64
#define P_       4096
#define KK       9
#define CK       2304
#define KC       64              // mod conv chunk
#define NITER    (CK / KC)       // 36
#define KCD      32              // dconv chunk
#define NITERD   (CK / KCD)      // 72

// ---------------- scratch ----------------------------------------------------
__device__ __align__(128) unsigned char g_wA[NITERD * 16384];  // fp16 A (dconv)
__device__ __align__(128) unsigned char g_wM[NITER * 4096];    // fp16 A (mod, M=32)
__device__ float4 g_mw[B_ * P_ * KK];
__device__ int4   g_mi[B_ * P_ * KK];

// ---------------- PTX helpers (portable ISA) ---------------------------------
__device__ __forceinline__ uint32_t smem_u32(const void* p) {
    uint32_t a;
    asm("{ .reg .u64 t; cvta.to.shared.u64 t, %1; cvt.u32.u64 %0, t; }" : "=r"(a) : "l"(p));
    return a;
}
__device__ __forceinline__ void ldsm4(uint32_t* r, uint32_t addr) {
    asm volatile("ldmatrix.sync.aligned.m8n8.x4.shared.b16 {%0,%1,%2,%3}, [%4];"
                 : "=r"(r[0]), "=r"(r[1]), "=r"(r[2]), "=r"(r[3]) : "r"(addr));
}
__device__ __forceinline__ void mma_f16(float* d, const uint32_t* a, const uint32_t* b) {
    asm volatile("mma.sync.aligned.m16n8k16.row.col.f32.f16.f16.f32 "
                 "{%0,%1,%2,%3}, {%4,%5,%6,%7}, {%8,%9}, {%0,%1,%2,%3};"
                 : "+f"(d[0]), "+f"(d[1]), "+f"(d[2]), "+f"(d[3])
                 : "r"(a[0]), "r"(a[1]), "r"(a[2]), "r"(a[3]), "r"(b[0]), "r"(b[1]));
}
__device__ __forceinline__ void cpasync16(uint32_t dst, const void* src) {
    asm volatile("cp.async.cg.shared.global [%0], [%1], 16;" :: "r"(dst), "l"(src));
}
#define CP_COMMIT()  asm volatile("cp.async.commit_group;" ::: "memory")
#define CP_WAIT(n)   asm volatile("cp.async.wait_group %0;" :: "n"(n) : "memory")

// ---------------- smem layouts ------------------------------------------------
// dconv_tc (101376 B): A 3x16384 | B 3x8192 | meta float4 + ushort4 (round-12)
#define AS_OFF   0
#define BS_OFF   49152
#define MW_OFF   73728             // float4[9][128]
#define MI_OFF   92160             // ushort4[9][128]
#define SMEM_BYTES_D 101376
// mod_tc (77824 B): stage s at s*20480 (A 4096 | B 16384), C at 61440
#define MA(s)    ((s) * 20480)
#define MB(s)    ((s) * 20480 + 4096)
#define MCS_OFF  61440
#define MSMEM_BYTES 77824

// ---------------- kernel 0: prep both A images -------------------------------
__global__ __launch_bounds__(256) void prep_w(const float* __restrict__ wdef,
                                              const float* __restrict__ wmod) {
    int blk = blockIdx.x;
    if (blk < 2304) {
        int idx = blk * 256 + threadIdx.x;
        int o = idx / CK, ck = idx - o * CK;
        __half h = __float2half_rn(wdef[idx]);
        int it = ck >> 5, kl = ck & 31;
        int Mblk = o >> 4, Kb = kl >> 4;
        int a_idx = ((o >> 3) & 1) + 2 * ((kl >> 3) & 1);
        uint32_t byte = (uint32_t)it * 16384u
                      + (uint32_t)(((Mblk * 2 + Kb) * 4 + a_idx) * 128)
                      + (uint32_t)((o & 7) * 16 + (kl & 7) * 2);
        *(unsigned short*)(g_wA + byte) = __half_as_ushort(h);
    } else {
        int idx = (blk - 2304) * 256 + threadIdx.x;
        if (idx >= 32 * CK) return;
        int j = idx / CK, ck = idx - j * CK;
        float v = (j < 27) ? wmod[j * CK + ck] : 0.f;
        __half h = __float2half_rn(v);
        int it = ck >> 6, kl = ck & 63;
        int Mblk = j >> 4, Kb = kl >> 4;
        int a_idx = ((j >> 3) & 1) + 2 * ((kl >> 3) & 1);
        uint32_t byte = (uint32_t)it * 4096u
                      + (uint32_t)(((Mblk * 4 + Kb) * 4 + a_idx) * 128)
                      + (uint32_t)((j & 7) * 16 + (kl & 7) * 2);
        *(unsigned short*)(g_wM + byte) = __half_as_ushort(h);
    }
}

// ---------------- kernel 1: mod conv fp16 1-pass HMMA (serialized skeleton) --
// CTA: M=32 (27 used), N=128 px. 256 thr = 8 warps (2M x 4N), warp tile 16x32.
__global__ __launch_bounds__(256, 1) void mod_tc(const float* __restrict__ x) {
    extern __shared__ __align__(1024) unsigned char sm[];
    const uint32_t sb = smem_u32(sm);
    const int t  = threadIdx.x;
    const int b  = blockIdx.z;
    const int p0 = blockIdx.x * 128;
    const float* xb = x + ((size_t)b << 20);

    const int lane = t & 31, warp = t >> 5;
    const int wm = warp >> 2, wn = warp & 3;

    float acc[4][4];
#pragma unroll
    for (int a = 0; a < 4; a++)
#pragma unroll
        for (int e = 0; e < 4; e++) acc[a][e] = 0.f;

    const int gp = t & 127;
    const int gq = t >> 7;                 // 0..1
    const int hh = (p0 + gp) >> 6, ww = (p0 + gp) & 63;

    auto produce = [&](int i) {
        const int s = i % 3;
        cpasync16(sb + MA(s) + t * 16, g_wM + (size_t)i * 4096 + t * 16);
        CP_COMMIT();
        unsigned char* bs = sm + MB(s);
        const int ck0 = i * KC;
#pragma unroll
        for (int j = 0; j < 16; j++) {
            int pp  = j * 2 + gq;
            int kk  = ck0 + pp * 2;
            int c0  = (kk * 7282) >> 16;  int tap0 = kk - c0 * 9;
            int kk1 = kk + 1;
            int c1  = (kk1 * 7282) >> 16; int tap1 = kk1 - c1 * 9;
            int ky0 = tap0 / 3, kx0 = tap0 - ky0 * 3;
            int ky1 = tap1 / 3, kx1 = tap1 - ky1 * 3;
            int y0 = hh + ky0 - 1, x0 = ww + kx0 - 1;
            int y1 = hh + ky1 - 1, x1 = ww + kx1 - 1;
            float v0 = 0.f, v1 = 0.f;
            if (y0 >= 0 && y0 < HW && x0 >= 0 && x0 < HW)
                v0 = __ldg(xb + ((size_t)c0 << 12) + (y0 << 6) + x0);
            if (y1 >= 0 && y1 < HW && x1 >= 0 && x1 < HW)
                v1 = __ldg(xb + ((size_t)c1 << 12) + (y1 << 6) + x1);
            __half2 hv = __floats2half2_rn(v0, v1);
            uint32_t byte = (uint32_t)(((gp >> 3) * 8 + (pp >> 2)) * 128
                                       + (gp & 7) * 16 + (pp & 3) * 4);
            *(uint32_t*)(bs + byte) = *(uint32_t*)&hv;
        }
    };

    auto consume = [&](int i) {
        const uint32_t as = sb + MA(i % 3);
        const uint32_t bs = sb + MB(i % 3);
        const uint32_t arow = (uint32_t)((lane & 7) * 16);
        const uint32_t gsel = (uint32_t)(lane >> 3);
#pragma unroll
        for (int kb = 0; kb < 4; kb++) {
            uint32_t af[4];
            uint32_t tb = (uint32_t)(((wm * 4 + kb) * 4 + gsel) * 128) + arow;
            ldsm4(af, as + tb);
#pragma unroll
            for (int jj = 0; jj < 2; jj++) {
                int nt = wn * 4 + jj * 2;
                uint32_t tb2 = (uint32_t)(((nt + (gsel >> 1)) * 8 + 2 * kb + (gsel & 1)) * 128) + arow;
                uint32_t bf[4];
                ldsm4(bf, bs + tb2);
#pragma unroll
                for (int nn = 0; nn < 2; nn++)
                    mma_f16(acc[jj * 2 + nn], af, bf + nn * 2);
            }
        }
    };

    produce(0);
    for (int i = 0; i < NITER; i++) {
        if (i + 1 < NITER) { produce(i + 1); CP_WAIT(1); }
        else               { CP_WAIT(0); }
        __syncthreads();
        consume(i);
    }

    // ---- epilogue: stage C, compute bilinear metadata -----------------------
    float* C = (float*)(sm + MCS_OFF);     // [32][128]
    __syncthreads();
    {
        int r0 = wm * 16 + (lane >> 2);
#pragma unroll
        for (int jj = 0; jj < 2; jj++)
#pragma unroll
            for (int nn = 0; nn < 2; nn++) {
                int col = wn * 32 + jj * 16 + nn * 8 + (lane & 3) * 2;
                float* dd = acc[jj * 2 + nn];
                C[r0 * 128 + col]           = dd[0];
                C[r0 * 128 + col + 1]       = dd[1];
                C[(r0 + 8) * 128 + col]     = dd[2];
                C[(r0 + 8) * 128 + col + 1] = dd[3];
            }
    }
    __syncthreads();

    for (int e = t; e < 128 * KK; e += 256) {
        int k = e >> 7, p = e & 127;
        float dy = C[(2 * k) * 128 + p];
        float dx = C[(2 * k + 1) * 128 + p];
        float mz = C[(18 + k) * 128 + p];
        float m  = 1.f / (1.f + expf(-mz));

        int ph = (p0 + p) >> 6, pw = (p0 + p) & 63;
        int ky = k / 3, kx = k - ky * 3;
        float py = dy + (float)(ph - 1 + ky);
        float px = dx + (float)(pw - 1 + kx);
        float y0f = floorf(py), x0f = floorf(px);
        float fy = py - y0f, fx = px - x0f;
        int y0 = (int)y0f, x0 = (int)x0f;
        int y1 = y0 + 1,  x1 = x0 + 1;

        bool vy0 = (y0 >= 0) & (y0 < HW);
        bool vy1 = (y1 >= 0) & (y1 < HW);
        bool vx0 = (x0 >= 0) & (x0 < HW);
        bool vx1 = (x1 >= 0) & (x1 < HW);
        int cy0 = min(max(y0, 0), HW - 1), cy1 = min(max(y1, 0), HW - 1);
        int cx0 = min(max(x0, 0), HW - 1), cx1 = min(max(x1, 0), HW - 1);

        float4 wv;
        wv.x = (vy0 && vx0) ? (1.f - fy) * (1.f - fx) * m : 0.f;
        wv.y = (vy0 && vx1) ? (1.f - fy) * fx         * m : 0.f;
        wv.z = (vy1 && vx0) ? fy * (1.f - fx)         * m : 0.f;
        wv.w = (vy1 && vx1) ? fy * fx                 * m : 0.f;
        int4 iv;
        iv.x = (cy0 << 6) + cx0;
        iv.y = (cy0 << 6) + cx1;
        iv.z = (cy1 << 6) + cx0;
        iv.w = (cy1 << 6) + cx1;

        g_mw[((size_t)b * P_ + p0 + p) * KK + k] = wv;
        g_mi[((size_t)b * P_ + p0 + p) * KK + k] = iv;
    }
}

// ---------------- kernel 2: software-pipelined fp16 HMMA GEMM (round-12) -----
__global__ __launch_bounds__(512, 1) void dconv_tc(const float* __restrict__ x,
                                                   const float* __restrict__ bias,
                                                   float* __restrict__ out) {
    extern __shared__ __align__(1024) unsigned char sm[];
    const uint32_t sb = smem_u32(sm);
    const int t  = threadIdx.x;
    const int b  = blockIdx.z;
    const int p0 = blockIdx.x * 128;
    const float* xb = x + ((size_t)b << 20);

    const int lane = t & 31, warp = t >> 5;
    const int wm = warp >> 1, wn = warp & 1;

    float4*  s_mw = (float4*)(sm + MW_OFF);
    ushort4* s_mi = (ushort4*)(sm + MI_OFF);
    {
        const float4* gw = g_mw + ((size_t)b * P_ + p0) * KK;
        const int4*   gi = g_mi + ((size_t)b * P_ + p0) * KK;
        for (int e = t; e < 128 * KK; e += 512) {
            int tap = e >> 7, p = e & 127;
            float4 w = gw[p * 9 + tap];
            int4   v = gi[p * 9 + tap];
            s_mw[e] = w;
            s_mi[e] = make_ushort4((unsigned short)v.x, (unsigned short)v.y,
                                   (unsigned short)v.z, (unsigned short)v.w);
        }
    }
    __syncthreads();

    float d[2][8][4];
#pragma unroll
    for (int a = 0; a < 2; a++)
#pragma unroll
        for (int c = 0; c < 8; c++)
#pragma unroll
            for (int e = 0; e < 4; e++) d[a][c][e] = 0.f;

    const int gp = t & 127;
    const int gq = t >> 7;
    float L[4][8];

    auto ldB = [&](int i) {
        const int ck0 = i * KCD;
#pragma unroll
        for (int j = 0; j < 4; j++) {
            int pp  = j * 4 + gq;
            int kk  = ck0 + pp * 2;
            int c0  = (kk * 7282) >> 16;  int tap0 = kk - c0 * 9;
            int kk1 = kk + 1;
            int c1  = (kk1 * 7282) >> 16; int tap1 = kk1 - c1 * 9;
            ushort4 i0 = s_mi[tap0 * 128 + gp];
            ushort4 i1 = s_mi[tap1 * 128 + gp];
            const float* xc0 = xb + ((size_t)c0 << 12);
            const float* xc1 = xb + ((size_t)c1 << 12);
            L[j][0] = __ldg(xc0 + i0.x); L[j][1] = __ldg(xc0 + i0.y);
            L[j][2] = __ldg(xc0 + i0.z); L[j][3] = __ldg(xc0 + i0.w);
            L[j][4] = __ldg(xc1 + i1.x); L[j][5] = __ldg(xc1 + i1.y);
            L[j][6] = __ldg(xc1 + i1.z); L[j][7] = __ldg(xc1 + i1.w);
        }
    };
    auto cvtB = [&](int i) {
        const int ck0 = i * KCD;
        unsigned char* bs = sm + BS_OFF + (i % 3) * 8192;
#pragma unroll
        for (int j = 0; j < 4; j++) {
            int pp  = j * 4 + gq;
            int kk  = ck0 + pp * 2;
            int c0  = (kk * 7282) >> 16;  int tap0 = kk - c0 * 9;
            int kk1 = kk + 1;
            int c1  = (kk1 * 7282) >> 16; int tap1 = kk1 - c1 * 9;
            float4 w0 = s_mw[tap0 * 128 + gp];
            float4 w1 = s_mw[tap1 * 128 + gp];
            float g0 = w0.x * L[j][0] + w0.y * L[j][1] + w0.z * L[j][2] + w0.w * L[j][3];
            float g1 = w1.x * L[j][4] + w1.y * L[j][5] + w1.z * L[j][6] + w1.w * L[j][7];
            __half2 hv = __floats2half2_rn(g0, g1);
            uint32_t byte = (uint32_t)(((gp >> 3) * 4 + (pp >> 2)) * 128
                                       + (gp & 7) * 16 + (pp & 3) * 4);
            *(uint32_t*)(bs + byte) = *(uint32_t*)&hv;
        }
    };
    auto cpA = [&](int i) {
        uint32_t dst = sb + AS_OFF + (i % 3) * 16384 + t * 32;
        const unsigned char* src = g_wA + (size_t)i * 16384 + t * 32;
        cpasync16(dst, src);
        cpasync16(dst + 16, src + 16);
        CP_COMMIT();
    };
    auto consume = [&](int i) {
        const uint32_t as = sb + AS_OFF + (i % 3) * 16384;
        const uint32_t bs = sb + BS_OFF + (i % 3) * 8192;
        const uint32_t arow = (uint32_t)((lane & 7) * 16);
        const uint32_t gsel = (uint32_t)(lane >> 3);
#pragma unroll
        for (int kb = 0; kb < 2; kb++) {
            uint32_t af[8];
#pragma unroll
            for (int mb = 0; mb < 2; mb++) {
                uint32_t tb = (uint32_t)((((wm * 2 + mb) * 2 + kb) * 4 + gsel) * 128) + arow;
                ldsm4(af + mb * 4, as + tb);
            }
#pragma unroll
            for (int jj = 0; jj < 4; jj++) {
                int nt = wn * 8 + jj * 2;
                uint32_t tb = (uint32_t)(((nt + (gsel >> 1)) * 4 + 2 * kb + (gsel & 1)) * 128) + arow;
                uint32_t bf[4];
                ldsm4(bf, bs + tb);
#pragma unroll
                for (int mb = 0; mb < 2; mb++) {
#pragma unroll
                    for (int nn = 0; nn < 2; nn++)
                        mma_f16(d[mb][jj * 2 + nn], af + mb * 4, bf + nn * 2);
                }
            }
        }
    };

    ldB(0);  cpA(0);
    cvtB(0);
    ldB(1);  cpA(1);
    CP_WAIT(1);
    __syncthreads();

    for (int i = 0; i < NITERD; i++) {
        consume(i);
        if (i + 1 < NITERD) cvtB(i + 1);
        if (i + 2 < NITERD) { ldB(i + 2); cpA(i + 2); CP_WAIT(1); }
        else                { CP_WAIT(0); }
        __syncthreads();
    }

    // epilogue
#pragma unroll
    for (int mb = 0; mb < 2; mb++) {
        int m0 = wm * 32 + mb * 16 + (lane >> 2);
        float bv0 = bias[m0], bv1 = bias[m0 + 8];
        float* r0 = out + (((size_t)(b * COUT + m0)) << 12) + p0 + wn * 64 + (lane & 3) * 2;
        float* r1 = r0 + ((size_t)8 << 12);
#pragma unroll
        for (int nj = 0; nj < 8; nj++) {
            float2 v0 = make_float2(d[mb][nj][0] + bv0, d[mb][nj][1] + bv0);
            float2 v1 = make_float2(d[mb][nj][2] + bv1, d[mb][nj][3] + bv1);
            *(float2*)(r0 + nj * 8) = v0;
            *(float2*)(r1 + nj * 8) = v1;
        }
    }
}

// ---------------- launch ------------------------------------------------------
extern "C" void kernel_launch(void* const* d_in, const int* in_sizes, int n_in,
                              void* d_out, int out_size) {
    const float* x     = (const float*)d_in[0];
    const float* w_mod = (const float*)d_in[1];
    const float* w_def = (const float*)d_in[2];
    const float* b_def = (const float*)d_in[3];
    float* out = (float*)d_out;

    cudaFuncSetAttribute(dconv_tc, cudaFuncAttributeMaxDynamicSharedMemorySize, SMEM_BYTES_D);
    cudaFuncSetAttribute(mod_tc,   cudaFuncAttributeMaxDynamicSharedMemorySize, MSMEM_BYTES);

    prep_w<<<2592, 256>>>(w_def, w_mod);
    mod_tc<<<dim3(P_ / 128, 1, B_), 256, MSMEM_BYTES>>>(x);
    dconv_tc<<<dim3(P_ / 128, 1, B_), 512, SMEM_BYTES_D>>>(x, b_def, out);
}

// round 16
// speedup vs baseline: 1.9186x; 1.2986x over previous
#include <cuda_runtime.h>
#include <cuda_fp16.h>
#include <math.h>
#include <stdint.h>

#define B_       4
#define CIN      256
#define COUT     256
#define HW       64
#define P_       4096
#define KK       9
#define CK       2304
#define KC       64              // mod conv chunk
#define NITER    (CK / KC)       // 36
#define KCD      32              // dconv chunk
#define NITERD   (CK / KCD)      // 72

// ---------------- scratch ----------------------------------------------------
__device__ __align__(128) unsigned char g_wA[NITERD * 16384];  // fp16 A (dconv, tap-major K)
__device__ __align__(128) unsigned char g_wM[NITER * 4096];    // fp16 A (mod, tap-major K)
__device__ float4 g_mw[B_ * P_ * KK];
__device__ int4   g_mi[B_ * P_ * KK];

// ---------------- PTX helpers (portable ISA) ---------------------------------
__device__ __forceinline__ uint32_t smem_u32(const void* p) {
    uint32_t a;
    asm("{ .reg .u64 t; cvta.to.shared.u64 t, %1; cvt.u32.u64 %0, t; }" : "=r"(a) : "l"(p));
    return a;
}
__device__ __forceinline__ void ldsm4(uint32_t* r, uint32_t addr) {
    asm volatile("ldmatrix.sync.aligned.m8n8.x4.shared.b16 {%0,%1,%2,%3}, [%4];"
                 : "=r"(r[0]), "=r"(r[1]), "=r"(r[2]), "=r"(r[3]) : "r"(addr));
}
__device__ __forceinline__ void mma_f16(float* d, const uint32_t* a, const uint32_t* b) {
    asm volatile("mma.sync.aligned.m16n8k16.row.col.f32.f16.f16.f32 "
                 "{%0,%1,%2,%3}, {%4,%5,%6,%7}, {%8,%9}, {%0,%1,%2,%3};"
                 : "+f"(d[0]), "+f"(d[1]), "+f"(d[2]), "+f"(d[3])
                 : "r"(a[0]), "r"(a[1]), "r"(a[2]), "r"(a[3]), "r"(b[0]), "r"(b[1]));
}
__device__ __forceinline__ void cpasync16(uint32_t dst, const void* src) {
    asm volatile("cp.async.cg.shared.global [%0], [%1], 16;" :: "r"(dst), "l"(src));
}
#define CP_COMMIT()  asm volatile("cp.async.commit_group;" ::: "memory")
#define CP_WAIT(n)   asm volatile("cp.async.wait_group %0;" :: "n"(n) : "memory")

// ---------------- smem layouts ------------------------------------------------
// dconv_tc (101376 B): A 3x16384 | B 3x8192 | meta float4 + ushort4 [tap][p]
#define AS_OFF   0
#define BS_OFF   49152
#define MW_OFF   73728             // float4[9][128]
#define MI_OFF   92160             // ushort4[9][128]
#define SMEM_BYTES_D 101376
// mod_tc (77824 B): stage s at s*20480 (A 4096 | B 16384), C at 61440
#define MA(s)    ((s) * 20480)
#define MB(s)    ((s) * 20480 + 4096)
#define MCS_OFF  61440
#define MSMEM_BYTES 77824

// ---------------- kernel 0: prep both A images (tap-major K) -----------------
__global__ __launch_bounds__(256) void prep_w(const float* __restrict__ wdef,
                                              const float* __restrict__ wmod) {
    int blk = blockIdx.x;
    if (blk < 2304) {
        int idx = blk * 256 + threadIdx.x;
        int o = idx / CK, ck = idx - o * CK;       // ck = c*9 + tap
        int c = ck / 9, tap = ck - c * 9;
        int kn = tap * 256 + c;                    // tap-major
        __half h = __float2half_rn(wdef[idx]);
        int it = kn >> 5, kl = kn & 31;
        int Mblk = o >> 4, Kb = kl >> 4;
        int a_idx = ((o >> 3) & 1) + 2 * ((kl >> 3) & 1);
        uint32_t byte = (uint32_t)it * 16384u
                      + (uint32_t)(((Mblk * 2 + Kb) * 4 + a_idx) * 128)
                      + (uint32_t)((o & 7) * 16 + (kl & 7) * 2);
        *(unsigned short*)(g_wA + byte) = __half_as_ushort(h);
    } else {
        int idx = (blk - 2304) * 256 + threadIdx.x;
        if (idx >= 32 * CK) return;
        int j = idx / CK, ck = idx - j * CK;
        int c = ck / 9, tap = ck - c * 9;
        int kn = tap * 256 + c;
        float v = (j < 27) ? wmod[j * CK + ck] : 0.f;
        __half h = __float2half_rn(v);
        int it = kn >> 6, kl = kn & 63;
        int Mblk = j >> 4, Kb = kl >> 4;
        int a_idx = ((j >> 3) & 1) + 2 * ((kl >> 3) & 1);
        uint32_t byte = (uint32_t)it * 4096u
                      + (uint32_t)(((Mblk * 4 + Kb) * 4 + a_idx) * 128)
                      + (uint32_t)((j & 7) * 16 + (kl & 7) * 2);
        *(unsigned short*)(g_wM + byte) = __half_as_ushort(h);
    }
}

// ---------------- kernel 1: mod conv fp16 1-pass HMMA (tap-major K) ----------
// One tap per iter: position/bounds computed once per produce.
__global__ __launch_bounds__(256, 1) void mod_tc(const float* __restrict__ x) {
    extern __shared__ __align__(1024) unsigned char sm[];
    const uint32_t sb = smem_u32(sm);
    const int t  = threadIdx.x;
    const int b  = blockIdx.z;
    const int p0 = blockIdx.x * 128;
    const float* xb = x + ((size_t)b << 20);

    const int lane = t & 31, warp = t >> 5;
    const int wm = warp >> 2, wn = warp & 3;

    float acc[4][4];
#pragma unroll
    for (int a = 0; a < 4; a++)
#pragma unroll
        for (int e = 0; e < 4; e++) acc[a][e] = 0.f;

    const int gp = t & 127;
    const int gq = t >> 7;                 // 0..1
    const int hh = (p0 + gp) >> 6, ww = (p0 + gp) & 63;

    auto produce = [&](int i) {
        const int s = i % 3;
        cpasync16(sb + MA(s) + t * 16, g_wM + (size_t)i * 4096 + t * 16);
        CP_COMMIT();
        unsigned char* bs = sm + MB(s);
        const int tap = i >> 2;            // KC=64: 4 iters per tap
        const int cb  = (i & 3) * 64;
        const int ky = tap / 3, kx = tap - ky * 3;
        const int y = hh + ky - 1, xx2 = ww + kx - 1;
        const bool ok = (y >= 0) & (y < HW) & (xx2 >= 0) & (xx2 < HW);
        const int off = (y << 6) + xx2;
        const float* xp = xb + off;
#pragma unroll
        for (int j = 0; j < 16; j++) {
            int pp = j * 2 + gq;
            int c  = cb + pp * 2;
            float v0 = 0.f, v1 = 0.f;
            if (ok) {
                v0 = __ldg(xp + ((size_t)c << 12));
                v1 = __ldg(xp + ((size_t)(c + 1) << 12));
            }
            __half2 hv = __floats2half2_rn(v0, v1);
            uint32_t byte = (uint32_t)(((gp >> 3) * 8 + (pp >> 2)) * 128
                                       + (gp & 7) * 16 + (pp & 3) * 4);
            *(uint32_t*)(bs + byte) = *(uint32_t*)&hv;
        }
    };

    auto consume = [&](int i) {
        const uint32_t as = sb + MA(i % 3);
        const uint32_t bs = sb + MB(i % 3);
        const uint32_t arow = (uint32_t)((lane & 7) * 16);
        const uint32_t gsel = (uint32_t)(lane >> 3);
#pragma unroll
        for (int kb = 0; kb < 4; kb++) {
            uint32_t af[4];
            uint32_t tb = (uint32_t)(((wm * 4 + kb) * 4 + gsel) * 128) + arow;
            ldsm4(af, as + tb);
#pragma unroll
            for (int jj = 0; jj < 2; jj++) {
                int nt = wn * 4 + jj * 2;
                uint32_t tb2 = (uint32_t)(((nt + (gsel >> 1)) * 8 + 2 * kb + (gsel & 1)) * 128) + arow;
                uint32_t bf[4];
                ldsm4(bf, bs + tb2);
#pragma unroll
                for (int nn = 0; nn < 2; nn++)
                    mma_f16(acc[jj * 2 + nn], af, bf + nn * 2);
            }
        }
    };

    produce(0);
    for (int i = 0; i < NITER; i++) {
        if (i + 1 < NITER) { produce(i + 1); CP_WAIT(1); }
        else               { CP_WAIT(0); }
        __syncthreads();
        consume(i);
    }

    // ---- epilogue: stage C, compute bilinear metadata -----------------------
    float* C = (float*)(sm + MCS_OFF);     // [32][128]
    __syncthreads();
    {
        int r0 = wm * 16 + (lane >> 2);
#pragma unroll
        for (int jj = 0; jj < 2; jj++)
#pragma unroll
            for (int nn = 0; nn < 2; nn++) {
                int col = wn * 32 + jj * 16 + nn * 8 + (lane & 3) * 2;
                float* dd = acc[jj * 2 + nn];
                C[r0 * 128 + col]           = dd[0];
                C[r0 * 128 + col + 1]       = dd[1];
                C[(r0 + 8) * 128 + col]     = dd[2];
                C[(r0 + 8) * 128 + col + 1] = dd[3];
            }
    }
    __syncthreads();

    for (int e = t; e < 128 * KK; e += 256) {
        int k = e >> 7, p = e & 127;
        float dy = C[(2 * k) * 128 + p];
        float dx = C[(2 * k + 1) * 128 + p];
        float mz = C[(18 + k) * 128 + p];
        float m  = 1.f / (1.f + expf(-mz));

        int ph = (p0 + p) >> 6, pw = (p0 + p) & 63;
        int ky = k / 3, kx = k - ky * 3;
        float py = dy + (float)(ph - 1 + ky);
        float px = dx + (float)(pw - 1 + kx);
        float y0f = floorf(py), x0f = floorf(px);
        float fy = py - y0f, fx = px - x0f;
        int y0 = (int)y0f, x0 = (int)x0f;
        int y1 = y0 + 1,  x1 = x0 + 1;

        bool vy0 = (y0 >= 0) & (y0 < HW);
        bool vy1 = (y1 >= 0) & (y1 < HW);
        bool vx0 = (x0 >= 0) & (x0 < HW);
        bool vx1 = (x1 >= 0) & (x1 < HW);
        int cy0 = min(max(y0, 0), HW - 1), cy1 = min(max(y1, 0), HW - 1);
        int cx0 = min(max(x0, 0), HW - 1), cx1 = min(max(x1, 0), HW - 1);

        float4 wv;
        wv.x = (vy0 && vx0) ? (1.f - fy) * (1.f - fx) * m : 0.f;
        wv.y = (vy0 && vx1) ? (1.f - fy) * fx         * m : 0.f;
        wv.z = (vy1 && vx0) ? fy * (1.f - fx)         * m : 0.f;
        wv.w = (vy1 && vx1) ? fy * fx                 * m : 0.f;
        int4 iv;
        iv.x = (cy0 << 6) + cx0;
        iv.y = (cy0 << 6) + cx1;
        iv.z = (cy1 << 6) + cx0;
        iv.w = (cy1 << 6) + cx1;

        g_mw[((size_t)b * P_ + p0 + p) * KK + k] = wv;
        g_mi[((size_t)b * P_ + p0 + p) * KK + k] = iv;
    }
}

// ---------------- kernel 2: software-pipelined fp16 HMMA GEMM (tap-major K) --
__global__ __launch_bounds__(512, 1) void dconv_tc(const float* __restrict__ x,
                                                   const float* __restrict__ bias,
                                                   float* __restrict__ out) {
    extern __shared__ __align__(1024) unsigned char sm[];
    const uint32_t sb = smem_u32(sm);
    const int t  = threadIdx.x;
    const int b  = blockIdx.z;
    const int p0 = blockIdx.x * 128;
    const float* xb = x + ((size_t)b << 20);

    const int lane = t & 31, warp = t >> 5;
    const int wm = warp >> 1, wn = warp & 1;

    float4*  s_mw = (float4*)(sm + MW_OFF);
    ushort4* s_mi = (ushort4*)(sm + MI_OFF);
    {
        const float4* gw = g_mw + ((size_t)b * P_ + p0) * KK;
        const int4*   gi = g_mi + ((size_t)b * P_ + p0) * KK;
        for (int e = t; e < 128 * KK; e += 512) {
            int tap = e >> 7, p = e & 127;
            float4 w = gw[p * 9 + tap];
            int4   v = gi[p * 9 + tap];
            s_mw[e] = w;
            s_mi[e] = make_ushort4((unsigned short)v.x, (unsigned short)v.y,
                                   (unsigned short)v.z, (unsigned short)v.w);
        }
    }
    __syncthreads();

    float d[2][8][4];
#pragma unroll
    for (int a = 0; a < 2; a++)
#pragma unroll
        for (int c = 0; c < 8; c++)
#pragma unroll
            for (int e = 0; e < 4; e++) d[a][c][e] = 0.f;

    const int gp = t & 127;
    const int gq = t >> 7;
    float L[4][8];

    // iter i covers K [i*32, i*32+32): tap = i>>3 (const), c = (i&7)*32 + local
    auto ldB = [&](int i) {
        const int tap = i >> 3;
        const int cb  = (i & 7) * 32;
        ushort4 iv = s_mi[tap * 128 + gp];      // ONE meta-index load per iter
#pragma unroll
        for (int j = 0; j < 4; j++) {
            int pp = j * 4 + gq;
            const float* xc0 = xb + ((size_t)(cb + pp * 2) << 12);
            const float* xc1 = xc0 + 4096;
            L[j][0] = __ldg(xc0 + iv.x); L[j][1] = __ldg(xc0 + iv.y);
            L[j][2] = __ldg(xc0 + iv.z); L[j][3] = __ldg(xc0 + iv.w);
            L[j][4] = __ldg(xc1 + iv.x); L[j][5] = __ldg(xc1 + iv.y);
            L[j][6] = __ldg(xc1 + iv.z); L[j][7] = __ldg(xc1 + iv.w);
        }
    };
    auto cvtB = [&](int i) {
        const int tap = i >> 3;
        unsigned char* bs = sm + BS_OFF + (i % 3) * 8192;
        float4 w = s_mw[tap * 128 + gp];        // ONE meta-weight load per iter
#pragma unroll
        for (int j = 0; j < 4; j++) {
            int pp = j * 4 + gq;
            float g0 = w.x * L[j][0] + w.y * L[j][1] + w.z * L[j][2] + w.w * L[j][3];
            float g1 = w.x * L[j][4] + w.y * L[j][5] + w.z * L[j][6] + w.w * L[j][7];
            __half2 hv = __floats2half2_rn(g0, g1);
            uint32_t byte = (uint32_t)(((gp >> 3) * 4 + (pp >> 2)) * 128
                                       + (gp & 7) * 16 + (pp & 3) * 4);
            *(uint32_t*)(bs + byte) = *(uint32_t*)&hv;
        }
    };
    auto cpA = [&](int i) {
        uint32_t dst = sb + AS_OFF + (i % 3) * 16384 + t * 32;
        const unsigned char* src = g_wA + (size_t)i * 16384 + t * 32;
        cpasync16(dst, src);
        cpasync16(dst + 16, src + 16);
        CP_COMMIT();
    };
    auto consume = [&](int i) {
        const uint32_t as = sb + AS_OFF + (i % 3) * 16384;
        const uint32_t bs = sb + BS_OFF + (i % 3) * 8192;
        const uint32_t arow = (uint32_t)((lane & 7) * 16);
        const uint32_t gsel = (uint32_t)(lane >> 3);
#pragma unroll
        for (int kb = 0; kb < 2; kb++) {
            uint32_t af[8];
#pragma unroll
            for (int mb = 0; mb < 2; mb++) {
                uint32_t tb = (uint32_t)((((wm * 2 + mb) * 2 + kb) * 4 + gsel) * 128) + arow;
                ldsm4(af + mb * 4, as + tb);
            }
#pragma unroll
            for (int jj = 0; jj < 4; jj++) {
                int nt = wn * 8 + jj * 2;
                uint32_t tb = (uint32_t)(((nt + (gsel >> 1)) * 4 + 2 * kb + (gsel & 1)) * 128) + arow;
                uint32_t bf[4];
                ldsm4(bf, bs + tb);
#pragma unroll
                for (int mb = 0; mb < 2; mb++) {
#pragma unroll
                    for (int nn = 0; nn < 2; nn++)
                        mma_f16(d[mb][jj * 2 + nn], af + mb * 4, bf + nn * 2);
                }
            }
        }
    };

    ldB(0);  cpA(0);
    cvtB(0);
    ldB(1);  cpA(1);
    CP_WAIT(1);
    __syncthreads();

    for (int i = 0; i < NITERD; i++) {
        consume(i);
        if (i + 1 < NITERD) cvtB(i + 1);
        if (i + 2 < NITERD) { ldB(i + 2); cpA(i + 2); CP_WAIT(1); }
        else                { CP_WAIT(0); }
        __syncthreads();
    }

    // epilogue
#pragma unroll
    for (int mb = 0; mb < 2; mb++) {
        int m0 = wm * 32 + mb * 16 + (lane >> 2);
        float bv0 = bias[m0], bv1 = bias[m0 + 8];
        float* r0 = out + (((size_t)(b * COUT + m0)) << 12) + p0 + wn * 64 + (lane & 3) * 2;
        float* r1 = r0 + ((size_t)8 << 12);
#pragma unroll
        for (int nj = 0; nj < 8; nj++) {
            float2 v0 = make_float2(d[mb][nj][0] + bv0, d[mb][nj][1] + bv0);
            float2 v1 = make_float2(d[mb][nj][2] + bv1, d[mb][nj][3] + bv1);
            *(float2*)(r0 + nj * 8) = v0;
            *(float2*)(r1 + nj * 8) = v1;
        }
    }
}

// ---------------- launch ------------------------------------------------------
extern "C" void kernel_launch(void* const* d_in, const int* in_sizes, int n_in,
                              void* d_out, int out_size) {
    const float* x     = (const float*)d_in[0];
    const float* w_mod = (const float*)d_in[1];
    const float* w_def = (const float*)d_in[2];
    const float* b_def = (const float*)d_in[3];
    float* out = (float*)d_out;

    cudaFuncSetAttribute(dconv_tc, cudaFuncAttributeMaxDynamicSharedMemorySize, SMEM_BYTES_D);
    cudaFuncSetAttribute(mod_tc,   cudaFuncAttributeMaxDynamicSharedMemorySize, MSMEM_BYTES);

    prep_w<<<2592, 256>>>(w_def, w_mod);
    mod_tc<<<dim3(P_ / 128, 1, B_), 256, MSMEM_BYTES>>>(x);
    dconv_tc<<<dim3(P_ / 128, 1, B_), 512, SMEM_BYTES_D>>>(x, b_def, out);
}